// round 1
// baseline (speedup 1.0000x reference)
#include <cuda_runtime.h>
#include <math.h>

// Problem constants (SimpleLanguageModel: B=2, T=2048, H=1024, V=32000, L=4)
#define BB 2
#define TT 2048
#define HH 1024
#define VV 32000
#define LL 4
#define MM (BB*TT)          // 4096 rows
#define NEG_SLOPE 0.01f

// ---------------- scratch (no allocations allowed -> __device__ globals) ----
__device__ float g_x [(size_t)MM*HH];
__device__ float g_q [(size_t)MM*HH];
__device__ float g_k [(size_t)MM*HH];
__device__ float g_v [(size_t)MM*HH];
__device__ float g_s [(size_t)BB*TT*TT];
__device__ float g_b0[(size_t)MM*HH];
__device__ float g_b1[(size_t)MM*HH];
__device__ float g_rowloss[MM];

// ---------------- embedding: x[b,t,:] = tok_emb[idx[b,t],:] + pos_emb[t,:] --
__global__ void embed_kernel(const int* __restrict__ idx,
                             const float* __restrict__ tok,
                             const float* __restrict__ pos,
                             float* __restrict__ x)
{
    int row = blockIdx.x;            // 0..MM-1
    int t   = row & (TT - 1);
    int token = idx[row];
    const float4* tp = (const float4*)(tok + (size_t)token * HH);
    const float4* pp = (const float4*)(pos + (size_t)t * HH);
    float4* xp = (float4*)(x + (size_t)row * HH);
    int i = threadIdx.x;             // 256 threads, HH/4 = 256
    float4 a = tp[i], b = pp[i];
    xp[i] = make_float4(a.x + b.x, a.y + b.y, a.z + b.z, a.w + b.w);
}

// ---------------- 128x128x8 fp32 tiled GEMM, 8x8 per thread --------------
// C[M,N] = act( alpha * A@B (+bias) )
// NT=false: B is row-major [K,N].  NT=true: B is row-major [N,K] (C=A@B^T).
// CAUSAL: skip tiles with blockIdx.x > blockIdx.y (upper-triangular tiles).
template<bool NT, bool CAUSAL, bool BIAS, bool LEAKY>
__global__ __launch_bounds__(256, 2)
void gemm128(const float* __restrict__ A, const float* __restrict__ B,
             const float* __restrict__ bias, float* __restrict__ C,
             int M, int N, int K,
             size_t sA, size_t sB, size_t sC, float alpha)
{
    int bn = blockIdx.x, bm = blockIdx.y, bz = blockIdx.z;
    if (CAUSAL && bn > bm) return;
    A += (size_t)bz * sA;  B += (size_t)bz * sB;  C += (size_t)bz * sC;

    __shared__ float As[8][128];
    __shared__ float Bs[8][128];

    int tid = threadIdx.x;
    int tx = tid & 15;       // 0..15 -> 8 cols each
    int ty = tid >> 4;       // 0..15 -> 8 rows each

    // load mapping: one float4 per thread per tile
    int aRow = tid >> 1;             // 0..127
    int aCol = (tid & 1) * 4;        // 0 or 4
    int bRow = tid >> 5;             // 0..7   (NN)
    int bCol = (tid & 31) * 4;       // 0..124 (NN)

    const float* Aptr = A + (size_t)(bm * 128 + aRow) * K + aCol;
    const float* Bptr = NT ? (B + (size_t)(bn * 128 + aRow) * K + aCol)
                           : (B + (size_t)bRow * N + (size_t)bn * 128 + bCol);

    float acc[8][8];
#pragma unroll
    for (int i = 0; i < 8; i++)
#pragma unroll
        for (int j = 0; j < 8; j++) acc[i][j] = 0.0f;

    for (int k0 = 0; k0 < K; k0 += 8) {
        float4 a = *(const float4*)(Aptr + k0);
        As[aCol + 0][aRow] = a.x;  As[aCol + 1][aRow] = a.y;
        As[aCol + 2][aRow] = a.z;  As[aCol + 3][aRow] = a.w;
        if (NT) {
            float4 b = *(const float4*)(Bptr + k0);
            Bs[aCol + 0][aRow] = b.x;  Bs[aCol + 1][aRow] = b.y;
            Bs[aCol + 2][aRow] = b.z;  Bs[aCol + 3][aRow] = b.w;
        } else {
            float4 b = *(const float4*)(Bptr + (size_t)k0 * N);
            *(float4*)&Bs[bRow][bCol] = b;
        }
        __syncthreads();
#pragma unroll
        for (int kk = 0; kk < 8; kk++) {
            float4 a0 = *(float4*)&As[kk][ty * 8];
            float4 a1 = *(float4*)&As[kk][ty * 8 + 4];
            float4 b0 = *(float4*)&Bs[kk][tx * 8];
            float4 b1 = *(float4*)&Bs[kk][tx * 8 + 4];
            float av[8] = {a0.x,a0.y,a0.z,a0.w,a1.x,a1.y,a1.z,a1.w};
            float bv[8] = {b0.x,b0.y,b0.z,b0.w,b1.x,b1.y,b1.z,b1.w};
#pragma unroll
            for (int i = 0; i < 8; i++)
#pragma unroll
                for (int j = 0; j < 8; j++)
                    acc[i][j] = fmaf(av[i], bv[j], acc[i][j]);
        }
        __syncthreads();
    }

    int row0 = bm * 128 + ty * 8;
    int col0 = bn * 128 + tx * 8;
    float bv[8];
    if (BIAS) {
#pragma unroll
        for (int j = 0; j < 8; j++) bv[j] = bias[col0 + j];
    }
#pragma unroll
    for (int i = 0; i < 8; i++) {
        float out[8];
#pragma unroll
        for (int j = 0; j < 8; j++) {
            float v = acc[i][j] * alpha;
            if (BIAS)  v += bv[j];
            if (LEAKY) v = (v >= 0.0f) ? v : NEG_SLOPE * v;
            out[j] = v;
        }
        float* cp = C + (size_t)(row0 + i) * N + col0;
        *(float4*)(cp)     = make_float4(out[0], out[1], out[2], out[3]);
        *(float4*)(cp + 4) = make_float4(out[4], out[5], out[6], out[7]);
    }
}

// ---------------- block reductions (256 threads) ----------------------------
__device__ __forceinline__ float warpMax(float v) {
#pragma unroll
    for (int o = 16; o > 0; o >>= 1) v = fmaxf(v, __shfl_xor_sync(0xffffffffu, v, o));
    return v;
}
__device__ __forceinline__ float warpSum(float v) {
#pragma unroll
    for (int o = 16; o > 0; o >>= 1) v += __shfl_xor_sync(0xffffffffu, v, o);
    return v;
}
__device__ float blockMax(float v) {
    __shared__ float sh[8];
    int lane = threadIdx.x & 31, w = threadIdx.x >> 5;
    v = warpMax(v);
    if (lane == 0) sh[w] = v;
    __syncthreads();
    if (w == 0) {
        float u = (lane < 8) ? sh[lane] : -INFINITY;
        u = warpMax(u);
        if (lane == 0) sh[0] = u;
    }
    __syncthreads();
    float r = sh[0];
    __syncthreads();
    return r;
}
__device__ float blockSum(float v) {
    __shared__ float sh[8];
    int lane = threadIdx.x & 31, w = threadIdx.x >> 5;
    v = warpSum(v);
    if (lane == 0) sh[w] = v;
    __syncthreads();
    if (w == 0) {
        float u = (lane < 8) ? sh[lane] : 0.0f;
        u = warpSum(u);
        if (lane == 0) sh[0] = u;
    }
    __syncthreads();
    float r = sh[0];
    __syncthreads();
    return r;
}

// ---------------- causal softmax over scores rows ---------------------------
// row q keeps [0..t], zeros [t+1..T) so the following NN GEMM is valid.
__global__ void softmax_causal(float* __restrict__ s)
{
    int row = blockIdx.x;                 // 0..MM-1
    int b = row >> 11;                    // /TT
    int t = row & (TT - 1);
    float* p = s + (size_t)b * TT * TT + (size_t)t * TT;
    int tid = threadIdx.x;

    float m = -INFINITY;
    for (int i = tid; i <= t; i += 256) m = fmaxf(m, p[i]);
    m = blockMax(m);

    float sum = 0.0f;
    for (int i = tid; i <= t; i += 256) sum += expf(p[i] - m);
    sum = blockSum(sum);

    float inv = 1.0f / sum;
    for (int i = tid; i < TT; i += 256)
        p[i] = (i <= t) ? expf(p[i] - m) * inv : 0.0f;
}

// ---------------- cross entropy: per-row lse - logit[target] ---------------
__global__ void ce_rows(const float* __restrict__ logits,
                        const int* __restrict__ tgt,
                        float* __restrict__ rl)
{
    int row = blockIdx.x;
    const float* p = logits + (size_t)row * VV;
    int tid = threadIdx.x;

    float m = -INFINITY;
    for (int i = tid; i < VV; i += 256) m = fmaxf(m, p[i]);
    m = blockMax(m);

    float s = 0.0f;
    for (int i = tid; i < VV; i += 256) s += expf(p[i] - m);
    s = blockSum(s);

    if (tid == 0) {
        float lse = m + logf(s);
        rl[row] = lse - p[tgt[row]];
    }
}

__global__ void loss_reduce(const float* __restrict__ rl, float* __restrict__ out)
{
    int tid = threadIdx.x;
    float s = 0.0f;
    for (int i = tid; i < MM; i += 256) s += rl[i];
    s = blockSum(s);
    if (tid == 0) out[0] = s / (float)MM;
}

// ---------------- driver ----------------------------------------------------
extern "C" void kernel_launch(void* const* d_in, const int* in_sizes, int n_in,
                              void* d_out, int out_size)
{
    const int*   idx = (const int*)  d_in[0];
    const int*   tgt = (const int*)  d_in[1];
    const float* tok = (const float*)d_in[2];
    const float* pos = (const float*)d_in[3];
    const float* wq  = (const float*)d_in[4];
    const float* wk  = (const float*)d_in[5];
    const float* wv  = (const float*)d_in[6];
    const float* hw  = (const float*)d_in[7];
    const float* hb  = (const float*)d_in[8];
    const float* lw  = (const float*)d_in[9];
    const float* lb  = (const float*)d_in[10];
    float* out = (float*)d_out;

    float *x, *q, *k, *v, *s, *b0, *b1, *rl;
    cudaGetSymbolAddress((void**)&x,  g_x);
    cudaGetSymbolAddress((void**)&q,  g_q);
    cudaGetSymbolAddress((void**)&k,  g_k);
    cudaGetSymbolAddress((void**)&v,  g_v);
    cudaGetSymbolAddress((void**)&s,  g_s);
    cudaGetSymbolAddress((void**)&b0, g_b0);
    cudaGetSymbolAddress((void**)&b1, g_b1);
    cudaGetSymbolAddress((void**)&rl, g_rowloss);

    // 1) embeddings
    embed_kernel<<<MM, 256>>>(idx, tok, pos, x);

    // 2) Q, K, V projections  [4096,1024] @ [1024,1024]
    dim3 g1(HH / 128, MM / 128);
    gemm128<false,false,false,false><<<g1, 256>>>(x, wq, nullptr, q, MM, HH, HH, 0,0,0, 1.0f);
    gemm128<false,false,false,false><<<g1, 256>>>(x, wk, nullptr, k, MM, HH, HH, 0,0,0, 1.0f);
    gemm128<false,false,false,false><<<g1, 256>>>(x, wv, nullptr, v, MM, HH, HH, 0,0,0, 1.0f);

    // 3) scores = Q @ K^T * H^-0.5, causal tiles only (per batch)
    dim3 gs(TT / 128, TT / 128, BB);
    gemm128<true,true,false,false><<<gs, 256>>>(q, k, nullptr, s, TT, TT, HH,
        (size_t)TT*HH, (size_t)TT*HH, (size_t)TT*TT, 0.03125f);

    // 4) causal softmax (zeros future positions)
    softmax_causal<<<MM, 256>>>(s);

    // 5) attn = wei @ V  (per batch)  [2048,2048] @ [2048,1024]
    dim3 ga(HH / 128, TT / 128, BB);
    gemm128<false,false,false,false><<<ga, 256>>>(s, v, nullptr, b0, TT, HH, TT,
        (size_t)TT*TT, (size_t)TT*HH, (size_t)TT*HH, 1.0f);

    // 6) MLP stack: Linear + bias + LeakyReLU, ping-pong b0 <-> b1
    float* cur = b0; float* nxt = b1;
    for (int l = 0; l < LL; l++) {
        gemm128<false,false,true,true><<<g1, 256>>>(cur, hw + (size_t)l*HH*HH,
            hb + (size_t)l*HH, nxt, MM, HH, HH, 0,0,0, 1.0f);
        float* tmp = cur; cur = nxt; nxt = tmp;
    }

    // 7) LM head -> logits straight into d_out  [4096,1024]@[1024,32000]+lb
    dim3 gh(VV / 128, MM / 128);
    gemm128<false,false,true,false><<<gh, 256>>>(cur, lw, lb, out, MM, VV, HH, 0,0,0, 1.0f);

    // 8) cross-entropy mean -> last output element
    ce_rows<<<MM, 256>>>(out, tgt, rl);
    loss_reduce<<<1, 256>>>(rl, out + (out_size - 1));
}

// round 4
// speedup vs baseline: 2.0767x; 2.0767x over previous
#include <cuda_runtime.h>
#include <cuda_bf16.h>
#include <math.h>
#include <stdint.h>

// Problem constants (SimpleLanguageModel: B=2, T=2048, H=1024, V=32000, L=4)
#define BB 2
#define TT 2048
#define HH 1024
#define VV 32000
#define LL 4
#define MM (BB*TT)          // 4096 rows
#define NEG_SLOPE 0.01f

// ---------------- scratch (no allocations allowed -> __device__ globals) ----
__device__ float g_x [(size_t)MM*HH];
__device__ float g_q [(size_t)MM*HH];
__device__ float g_k [(size_t)MM*HH];
__device__ float g_v [(size_t)MM*HH];
__device__ float g_s [(size_t)BB*TT*TT];
__device__ float g_b0[(size_t)MM*HH];
__device__ float g_b1[(size_t)MM*HH];
__device__ float g_rowloss[MM];
// bf16 hi/lo splits
__device__ __nv_bfloat16 g_ahi[(size_t)MM*HH];          // activations
__device__ __nv_bfloat16 g_alo[(size_t)MM*HH];
__device__ __nv_bfloat16 g_whi[(size_t)7*HH*HH];        // wq,wk,wv,hw0..3 (transposed [N,K])
__device__ __nv_bfloat16 g_wlo[(size_t)7*HH*HH];
__device__ __nv_bfloat16 g_bhi[(size_t)VV*HH];          // lw^T [V,H]
__device__ __nv_bfloat16 g_blo[(size_t)VV*HH];

// =============== bf16x3 mma.sync GEMM: C[M,N] = A[M,K] @ B[N,K]^T ==========
// A,B given as bf16 hi/lo splits (K=HH contiguous for both).
// D = Ahi*Bhi + Ahi*Blo + Alo*Bhi, fp32 accum via mma.sync m16n8k16.
// CTA 128x128, 8 warps (2x4), warp tile 64x32, K-chunk 32.
#define MMA_BF16(d, a, b) \
    asm volatile("mma.sync.aligned.m16n8k16.row.col.f32.bf16.bf16.f32 " \
        "{%0,%1,%2,%3}, {%4,%5,%6,%7}, {%8,%9}, {%0,%1,%2,%3};" \
        : "+f"((d)[0]), "+f"((d)[1]), "+f"((d)[2]), "+f"((d)[3]) \
        : "r"((a)[0]), "r"((a)[1]), "r"((a)[2]), "r"((a)[3]), \
          "r"((b)[0]), "r"((b)[1]))

template<bool BIAS, bool LEAKY>
__global__ __launch_bounds__(256, 2)
void mma_gemm(const __nv_bfloat16* __restrict__ Ahi, const __nv_bfloat16* __restrict__ Alo,
              const __nv_bfloat16* __restrict__ Bhi, const __nv_bfloat16* __restrict__ Blo,
              const float* __restrict__ bias, float* __restrict__ C, int N)
{
    const int K = HH;
    __shared__ __nv_bfloat16 sAh[128][40], sAl[128][40], sBh[128][40], sBl[128][40];

    int tid = threadIdx.x;
    int m0 = blockIdx.x * 128, n0 = blockIdx.y * 128;
    int lane = tid & 31, warp = tid >> 5;
    int wm = warp >> 2, wn = warp & 3;      // warp grid 2 (m) x 4 (n)
    int grp = lane >> 2, tg = lane & 3;

    float acc[4][4][4];
#pragma unroll
    for (int i = 0; i < 4; i++)
#pragma unroll
        for (int j = 0; j < 4; j++)
#pragma unroll
            for (int e = 0; e < 4; e++) acc[i][j][e] = 0.0f;

    for (int kc = 0; kc < K / 32; kc++) {
        int k0 = kc * 32;
        __syncthreads();                     // smem reuse guard
#pragma unroll
        for (int t = 0; t < 2; t++) {
            int u = tid + t * 256;
            int row = u >> 2, seg = (u & 3) * 8;
            size_t ga = (size_t)(m0 + row) * K + k0 + seg;
            size_t gb = (size_t)(n0 + row) * K + k0 + seg;
            *(uint4*)&sAh[row][seg] = *(const uint4*)(Ahi + ga);
            *(uint4*)&sAl[row][seg] = *(const uint4*)(Alo + ga);
            *(uint4*)&sBh[row][seg] = *(const uint4*)(Bhi + gb);
            *(uint4*)&sBl[row][seg] = *(const uint4*)(Blo + gb);
        }
        __syncthreads();

#pragma unroll
        for (int ks = 0; ks < 2; ks++) {
            int kb = ks * 16;
            uint32_t bh[4][2], bl[4][2];
#pragma unroll
            for (int nf = 0; nf < 4; nf++) {
                int n = wn * 32 + nf * 8 + grp;
                bh[nf][0] = *(uint32_t*)&sBh[n][kb + 2 * tg];
                bh[nf][1] = *(uint32_t*)&sBh[n][kb + 2 * tg + 8];
                bl[nf][0] = *(uint32_t*)&sBl[n][kb + 2 * tg];
                bl[nf][1] = *(uint32_t*)&sBl[n][kb + 2 * tg + 8];
            }
            uint32_t a[4][4];
            // hi pass: Ahi*Bhi + Ahi*Blo
#pragma unroll
            for (int mf = 0; mf < 4; mf++) {
                int r = wm * 64 + mf * 16 + grp;
                a[mf][0] = *(uint32_t*)&sAh[r    ][kb + 2 * tg];
                a[mf][1] = *(uint32_t*)&sAh[r + 8][kb + 2 * tg];
                a[mf][2] = *(uint32_t*)&sAh[r    ][kb + 2 * tg + 8];
                a[mf][3] = *(uint32_t*)&sAh[r + 8][kb + 2 * tg + 8];
            }
#pragma unroll
            for (int mf = 0; mf < 4; mf++)
#pragma unroll
                for (int nf = 0; nf < 4; nf++) {
                    MMA_BF16(acc[mf][nf], a[mf], bh[nf]);
                    MMA_BF16(acc[mf][nf], a[mf], bl[nf]);
                }
            // lo pass: Alo*Bhi
#pragma unroll
            for (int mf = 0; mf < 4; mf++) {
                int r = wm * 64 + mf * 16 + grp;
                a[mf][0] = *(uint32_t*)&sAl[r    ][kb + 2 * tg];
                a[mf][1] = *(uint32_t*)&sAl[r + 8][kb + 2 * tg];
                a[mf][2] = *(uint32_t*)&sAl[r    ][kb + 2 * tg + 8];
                a[mf][3] = *(uint32_t*)&sAl[r + 8][kb + 2 * tg + 8];
            }
#pragma unroll
            for (int mf = 0; mf < 4; mf++)
#pragma unroll
                for (int nf = 0; nf < 4; nf++)
                    MMA_BF16(acc[mf][nf], a[mf], bh[nf]);
        }
    }

    // epilogue: optional bias + leaky, fp32 out
#pragma unroll
    for (int mf = 0; mf < 4; mf++) {
        int r = m0 + wm * 64 + mf * 16 + grp;
#pragma unroll
        for (int nf = 0; nf < 4; nf++) {
            int c = n0 + wn * 32 + nf * 8 + 2 * tg;
            float b0v = 0.0f, b1v = 0.0f;
            if (BIAS) { b0v = bias[c]; b1v = bias[c + 1]; }
            float v0 = acc[mf][nf][0] + b0v;
            float v1 = acc[mf][nf][1] + b1v;
            float v2 = acc[mf][nf][2] + b0v;
            float v3 = acc[mf][nf][3] + b1v;
            if (LEAKY) {
                v0 = (v0 >= 0.0f) ? v0 : NEG_SLOPE * v0;
                v1 = (v1 >= 0.0f) ? v1 : NEG_SLOPE * v1;
                v2 = (v2 >= 0.0f) ? v2 : NEG_SLOPE * v2;
                v3 = (v3 >= 0.0f) ? v3 : NEG_SLOPE * v3;
            }
            *(float2*)(C + (size_t)r * N + c)       = make_float2(v0, v1);
            *(float2*)(C + (size_t)(r + 8) * N + c) = make_float2(v2, v3);
        }
    }
}

// ---------------- fp32 -> bf16 hi/lo split --------------------------------
__global__ void convert_hilo(const float* __restrict__ x,
                             __nv_bfloat16* __restrict__ hi,
                             __nv_bfloat16* __restrict__ lo)
{
    int i = blockIdx.x * blockDim.x + threadIdx.x;
    float v = x[i];
    __nv_bfloat16 h = __float2bfloat16(v);
    hi[i] = h;
    lo[i] = __float2bfloat16(v - __bfloat162float(h));
}

// transpose W[K][N] -> hi/lo [N][K]
__global__ void transpose_convert(const float* __restrict__ W,
                                  __nv_bfloat16* __restrict__ hi,
                                  __nv_bfloat16* __restrict__ lo,
                                  int K, int N)
{
    __shared__ float tile[32][33];
    int n0 = blockIdx.x * 32, k0 = blockIdx.y * 32;
    int tx = threadIdx.x, ty = threadIdx.y;   // 32 x 8
#pragma unroll
    for (int i = 0; i < 4; i++)
        tile[ty + i * 8][tx] = W[(size_t)(k0 + ty + i * 8) * N + n0 + tx];
    __syncthreads();
#pragma unroll
    for (int i = 0; i < 4; i++) {
        float x = tile[tx][ty + i * 8];       // = W[k0+tx][n0+ty+i*8]
        __nv_bfloat16 h = __float2bfloat16(x);
        size_t o = (size_t)(n0 + ty + i * 8) * K + k0 + tx;
        hi[o] = h;
        lo[o] = __float2bfloat16(x - __bfloat162float(h));
    }
}

// ---------------- embedding -------------------------------------------------
__global__ void embed_kernel(const int* __restrict__ idx,
                             const float* __restrict__ tok,
                             const float* __restrict__ pos,
                             float* __restrict__ x)
{
    int row = blockIdx.x;
    int t   = row & (TT - 1);
    int token = idx[row];
    const float4* tp = (const float4*)(tok + (size_t)token * HH);
    const float4* pp = (const float4*)(pos + (size_t)t * HH);
    float4* xp = (float4*)(x + (size_t)row * HH);
    int i = threadIdx.x;
    float4 a = tp[i], b = pp[i];
    xp[i] = make_float4(a.x + b.x, a.y + b.y, a.z + b.z, a.w + b.w);
}

// ---------------- fp32 SIMT tiled GEMM (attention path) ---------------------
template<bool NT, bool CAUSAL>
__global__ __launch_bounds__(256, 2)
void gemm128(const float* __restrict__ A, const float* __restrict__ B,
             float* __restrict__ C, int M, int N, int K,
             size_t sA, size_t sB, size_t sC, float alpha)
{
    int bn = blockIdx.x, bm = blockIdx.y, bz = blockIdx.z;
    if (CAUSAL && bn > bm) return;
    A += (size_t)bz * sA;  B += (size_t)bz * sB;  C += (size_t)bz * sC;

    __shared__ float As[8][128];
    __shared__ float Bs[8][128];

    int tid = threadIdx.x;
    int tx = tid & 15;
    int ty = tid >> 4;

    int aRow = tid >> 1;
    int aCol = (tid & 1) * 4;
    int bRow = tid >> 5;
    int bCol = (tid & 31) * 4;

    const float* Aptr = A + (size_t)(bm * 128 + aRow) * K + aCol;
    const float* Bptr = NT ? (B + (size_t)(bn * 128 + aRow) * K + aCol)
                           : (B + (size_t)bRow * N + (size_t)bn * 128 + bCol);

    float acc[8][8];
#pragma unroll
    for (int i = 0; i < 8; i++)
#pragma unroll
        for (int j = 0; j < 8; j++) acc[i][j] = 0.0f;

    for (int k0 = 0; k0 < K; k0 += 8) {
        float4 a = *(const float4*)(Aptr + k0);
        As[aCol + 0][aRow] = a.x;  As[aCol + 1][aRow] = a.y;
        As[aCol + 2][aRow] = a.z;  As[aCol + 3][aRow] = a.w;
        if (NT) {
            float4 b = *(const float4*)(Bptr + k0);
            Bs[aCol + 0][aRow] = b.x;  Bs[aCol + 1][aRow] = b.y;
            Bs[aCol + 2][aRow] = b.z;  Bs[aCol + 3][aRow] = b.w;
        } else {
            float4 b = *(const float4*)(Bptr + (size_t)k0 * N);
            *(float4*)&Bs[bRow][bCol] = b;
        }
        __syncthreads();
#pragma unroll
        for (int kk = 0; kk < 8; kk++) {
            float4 a0 = *(float4*)&As[kk][ty * 8];
            float4 a1 = *(float4*)&As[kk][ty * 8 + 4];
            float4 b0 = *(float4*)&Bs[kk][tx * 8];
            float4 b1 = *(float4*)&Bs[kk][tx * 8 + 4];
            float av[8] = {a0.x,a0.y,a0.z,a0.w,a1.x,a1.y,a1.z,a1.w};
            float bv[8] = {b0.x,b0.y,b0.z,b0.w,b1.x,b1.y,b1.z,b1.w};
#pragma unroll
            for (int i = 0; i < 8; i++)
#pragma unroll
                for (int j = 0; j < 8; j++)
                    acc[i][j] = fmaf(av[i], bv[j], acc[i][j]);
        }
        __syncthreads();
    }

    int row0 = bm * 128 + ty * 8;
    int col0 = bn * 128 + tx * 8;
#pragma unroll
    for (int i = 0; i < 8; i++) {
        float out[8];
#pragma unroll
        for (int j = 0; j < 8; j++) out[j] = acc[i][j] * alpha;
        float* cp = C + (size_t)(row0 + i) * N + col0;
        *(float4*)(cp)     = make_float4(out[0], out[1], out[2], out[3]);
        *(float4*)(cp + 4) = make_float4(out[4], out[5], out[6], out[7]);
    }
}

// ---------------- reductions ------------------------------------------------
__device__ __forceinline__ float warpMax(float v) {
#pragma unroll
    for (int o = 16; o > 0; o >>= 1) v = fmaxf(v, __shfl_xor_sync(0xffffffffu, v, o));
    return v;
}
__device__ __forceinline__ float warpSum(float v) {
#pragma unroll
    for (int o = 16; o > 0; o >>= 1) v += __shfl_xor_sync(0xffffffffu, v, o);
    return v;
}
__device__ float blockMax(float v) {
    __shared__ float sh[8];
    int lane = threadIdx.x & 31, w = threadIdx.x >> 5;
    v = warpMax(v);
    if (lane == 0) sh[w] = v;
    __syncthreads();
    if (w == 0) {
        float u = (lane < 8) ? sh[lane] : -INFINITY;
        u = warpMax(u);
        if (lane == 0) sh[0] = u;
    }
    __syncthreads();
    float r = sh[0];
    __syncthreads();
    return r;
}
__device__ float blockSum(float v) {
    __shared__ float sh[8];
    int lane = threadIdx.x & 31, w = threadIdx.x >> 5;
    v = warpSum(v);
    if (lane == 0) sh[w] = v;
    __syncthreads();
    if (w == 0) {
        float u = (lane < 8) ? sh[lane] : 0.0f;
        u = warpSum(u);
        if (lane == 0) sh[0] = u;
    }
    __syncthreads();
    float r = sh[0];
    __syncthreads();
    return r;
}

// ---------------- causal softmax --------------------------------------------
__global__ void softmax_causal(float* __restrict__ s)
{
    int row = blockIdx.x;
    int b = row >> 11;
    int t = row & (TT - 1);
    float* p = s + (size_t)b * TT * TT + (size_t)t * TT;
    int tid = threadIdx.x;

    float m = -INFINITY;
    for (int i = tid; i <= t; i += 256) m = fmaxf(m, p[i]);
    m = blockMax(m);

    float sum = 0.0f;
    for (int i = tid; i <= t; i += 256) sum += expf(p[i] - m);
    sum = blockSum(sum);

    float inv = 1.0f / sum;
    for (int i = tid; i < TT; i += 256)
        p[i] = (i <= t) ? expf(p[i] - m) * inv : 0.0f;
}

// ---------------- cross entropy ---------------------------------------------
__global__ void ce_rows(const float* __restrict__ logits,
                        const int* __restrict__ tgt,
                        float* __restrict__ rl)
{
    int row = blockIdx.x;
    const float* p = logits + (size_t)row * VV;
    int tid = threadIdx.x;

    float m = -INFINITY;
    for (int i = tid; i < VV; i += 256) m = fmaxf(m, p[i]);
    m = blockMax(m);

    float s = 0.0f;
    for (int i = tid; i < VV; i += 256) s += expf(p[i] - m);
    s = blockSum(s);

    if (tid == 0) {
        float lse = m + logf(s);
        rl[row] = lse - p[tgt[row]];
    }
}

__global__ void loss_reduce(const float* __restrict__ rl, float* __restrict__ out)
{
    int tid = threadIdx.x;
    float s = 0.0f;
    for (int i = tid; i < MM; i += 256) s += rl[i];
    s = blockSum(s);
    if (tid == 0) out[0] = s / (float)MM;
}

// ---------------- driver ----------------------------------------------------
extern "C" void kernel_launch(void* const* d_in, const int* in_sizes, int n_in,
                              void* d_out, int out_size)
{
    const int*   idx = (const int*)  d_in[0];
    const int*   tgt = (const int*)  d_in[1];
    const float* tok = (const float*)d_in[2];
    const float* pos = (const float*)d_in[3];
    const float* wq  = (const float*)d_in[4];
    const float* wk  = (const float*)d_in[5];
    const float* wv  = (const float*)d_in[6];
    const float* hw  = (const float*)d_in[7];
    const float* hb  = (const float*)d_in[8];
    const float* lw  = (const float*)d_in[9];
    const float* lb  = (const float*)d_in[10];
    float* out = (float*)d_out;

    float *x, *q, *k, *v, *s, *b0, *b1, *rl;
    __nv_bfloat16 *ahi, *alo, *whi, *wlo, *bhi, *blo;
    cudaGetSymbolAddress((void**)&x,  g_x);
    cudaGetSymbolAddress((void**)&q,  g_q);
    cudaGetSymbolAddress((void**)&k,  g_k);
    cudaGetSymbolAddress((void**)&v,  g_v);
    cudaGetSymbolAddress((void**)&s,  g_s);
    cudaGetSymbolAddress((void**)&b0, g_b0);
    cudaGetSymbolAddress((void**)&b1, g_b1);
    cudaGetSymbolAddress((void**)&rl, g_rowloss);
    cudaGetSymbolAddress((void**)&ahi, g_ahi);
    cudaGetSymbolAddress((void**)&alo, g_alo);
    cudaGetSymbolAddress((void**)&whi, g_whi);
    cudaGetSymbolAddress((void**)&wlo, g_wlo);
    cudaGetSymbolAddress((void**)&bhi, g_bhi);
    cudaGetSymbolAddress((void**)&blo, g_blo);

    dim3 tb(32, 8);
    const size_t WSZ = (size_t)HH * HH;

    // 0) weight preprocessing: transpose + hi/lo split
    transpose_convert<<<dim3(HH/32, HH/32), tb>>>(wq, whi + 0*WSZ, wlo + 0*WSZ, HH, HH);
    transpose_convert<<<dim3(HH/32, HH/32), tb>>>(wk, whi + 1*WSZ, wlo + 1*WSZ, HH, HH);
    transpose_convert<<<dim3(HH/32, HH/32), tb>>>(wv, whi + 2*WSZ, wlo + 2*WSZ, HH, HH);
    for (int l = 0; l < LL; l++)
        transpose_convert<<<dim3(HH/32, HH/32), tb>>>(hw + l*WSZ, whi + (3+l)*WSZ, wlo + (3+l)*WSZ, HH, HH);
    transpose_convert<<<dim3(VV/32, HH/32), tb>>>(lw, bhi, blo, HH, VV);

    // 1) embeddings + activation split
    embed_kernel<<<MM, 256>>>(idx, tok, pos, x);
    convert_hilo<<<(MM*HH)/256, 256>>>(x, ahi, alo);

    // 2) Q, K, V projections on tensor cores
    dim3 g1(MM/128, HH/128);
    mma_gemm<false,false><<<g1, 256>>>(ahi, alo, whi + 0*WSZ, wlo + 0*WSZ, nullptr, q, HH);
    mma_gemm<false,false><<<g1, 256>>>(ahi, alo, whi + 1*WSZ, wlo + 1*WSZ, nullptr, k, HH);
    mma_gemm<false,false><<<g1, 256>>>(ahi, alo, whi + 2*WSZ, wlo + 2*WSZ, nullptr, v, HH);

    // 3) scores = Q @ K^T * H^-0.5 (fp32, causal tiles only)
    dim3 gs(TT/128, TT/128, BB);
    gemm128<true,true><<<gs, 256>>>(q, k, s, TT, TT, HH,
        (size_t)TT*HH, (size_t)TT*HH, (size_t)TT*TT, 0.03125f);

    // 4) causal softmax
    softmax_causal<<<MM, 256>>>(s);

    // 5) attn = wei @ V (fp32)
    dim3 ga(HH/128, TT/128, BB);
    gemm128<false,false><<<ga, 256>>>(s, v, b0, TT, HH, TT,
        (size_t)TT*TT, (size_t)TT*HH, (size_t)TT*HH, 1.0f);

    // 6) MLP stack on tensor cores (bias + LeakyReLU fused)
    float* cur = b0; float* nxt = b1;
    for (int l = 0; l < LL; l++) {
        convert_hilo<<<(MM*HH)/256, 256>>>(cur, ahi, alo);
        mma_gemm<true,true><<<g1, 256>>>(ahi, alo, whi + (3+l)*WSZ, wlo + (3+l)*WSZ,
                                         hb + (size_t)l*HH, nxt, HH);
        float* tmp = cur; cur = nxt; nxt = tmp;
    }

    // 7) LM head on tensor cores (bias fused), logits -> d_out
    convert_hilo<<<(MM*HH)/256, 256>>>(cur, ahi, alo);
    mma_gemm<true,false><<<dim3(MM/128, VV/128), 256>>>(ahi, alo, bhi, blo, lb, out, VV);

    // 8) cross-entropy mean -> last output element
    ce_rows<<<MM, 256>>>(out, tgt, rl);
    loss_reduce<<<1, 256>>>(rl, out + (out_size - 1));
}

// round 5
// speedup vs baseline: 2.5520x; 1.2289x over previous
#include <cuda_runtime.h>
#include <cuda_bf16.h>
#include <math.h>
#include <stdint.h>

// Problem constants (SimpleLanguageModel: B=2, T=2048, H=1024, V=32000, L=4)
#define BB 2
#define TT 2048
#define HH 1024
#define VV 32000
#define LL 4
#define MM (BB*TT)          // 4096 rows
#define NEG_SLOPE 0.01f

typedef __nv_bfloat16 bf16;

// ---------------- scratch (no allocations allowed -> __device__ globals) ----
__device__ float g_x [(size_t)MM*HH];
__device__ float g_v [(size_t)MM*HH];
__device__ float g_s [(size_t)BB*TT*TT];
__device__ float g_rowloss[MM];
// bf16 hi/lo splits
__device__ bf16 g_ahi [(size_t)MM*HH];   // activation ping
__device__ bf16 g_alo [(size_t)MM*HH];
__device__ bf16 g_a2hi[(size_t)MM*HH];   // activation pong
__device__ bf16 g_a2lo[(size_t)MM*HH];
__device__ bf16 g_qhi [(size_t)MM*HH];
__device__ bf16 g_qlo [(size_t)MM*HH];
__device__ bf16 g_khi [(size_t)MM*HH];
__device__ bf16 g_klo [(size_t)MM*HH];
__device__ bf16 g_vthi[(size_t)MM*HH];   // V^T per batch [H,T]
__device__ bf16 g_vtlo[(size_t)MM*HH];
__device__ bf16 g_shi [(size_t)BB*TT*TT]; // softmax weights
__device__ bf16 g_slo [(size_t)BB*TT*TT];
__device__ bf16 g_whi [(size_t)7*HH*HH]; // wq,wk,wv,hw0..3 transposed [N,K]
__device__ bf16 g_wlo [(size_t)7*HH*HH];
__device__ bf16 g_bhi [(size_t)VV*HH];   // lw^T [V,H]
__device__ bf16 g_blo [(size_t)VV*HH];

// =============== bf16x3 mma.sync GEMM: C[M,N] = alpha*A[M,K]@B[N,K]^T ======
// 2-stage cp.async pipeline, CTA 128x128, 8 warps, warp tile 64x32.
#define MMA_BF16(d, a, b) \
    asm volatile("mma.sync.aligned.m16n8k16.row.col.f32.bf16.bf16.f32 " \
        "{%0,%1,%2,%3}, {%4,%5,%6,%7}, {%8,%9}, {%0,%1,%2,%3};" \
        : "+f"((d)[0]), "+f"((d)[1]), "+f"((d)[2]), "+f"((d)[3]) \
        : "r"((a)[0]), "r"((a)[1]), "r"((a)[2]), "r"((a)[3]), \
          "r"((b)[0]), "r"((b)[1]))

__device__ __forceinline__ void cp16(uint32_t dst, const void* src) {
    asm volatile("cp.async.cg.shared.global [%0], [%1], 16;" :: "r"(dst), "l"(src));
}
#define CP_COMMIT() asm volatile("cp.async.commit_group;" ::: "memory")
#define CP_WAIT(n)  asm volatile("cp.async.wait_group %0;" :: "n"(n) : "memory")

// smem layout (elements): stage stride 20480; arrays Ah 0, Al 5120, Bh 10240, Bl 15360
#define STG_EL 20480
#define ARR_EL 5120

template<bool CAUSAL, bool KCAUS, bool BIAS, bool LEAKY, bool OUTSPLIT>
__global__ __launch_bounds__(256, 2)
void mma_gemm(const bf16* __restrict__ Ahi, const bf16* __restrict__ Alo,
              const bf16* __restrict__ Bhi, const bf16* __restrict__ Blo,
              const float* __restrict__ bias,
              float* __restrict__ C, bf16* __restrict__ Chi, bf16* __restrict__ Clo,
              int N, int K, size_t sA, size_t sB, size_t sC, float alpha)
{
    int bm = blockIdx.x, bn = blockIdx.y, bz = blockIdx.z;
    if (CAUSAL && bn > bm) return;
    const bf16* Ah = Ahi + bz * sA;  const bf16* Al = Alo + bz * sA;
    const bf16* Bh = Bhi + bz * sB;  const bf16* Bl = Blo + bz * sB;

    extern __shared__ bf16 smem[];
    uint32_t sbase = (uint32_t)__cvta_generic_to_shared(smem);

    int tid = threadIdx.x;
    int m0 = bm * 128, n0 = bn * 128;
    int lane = tid & 31, warp = tid >> 5;
    int wm = warp >> 2, wn = warp & 3;      // warp grid 2 (m) x 4 (n)
    int grp = lane >> 2, tg = lane & 3;

    int KC = K / 32;
    if (KCAUS) { int kcm = (m0 + 128) / 32; if (kcm < KC) KC = kcm; }

    // async load of one 128x32 chunk of all 4 arrays into stage st
    auto load_chunk = [&](int kc, int st) {
        int k0 = kc * 32;
        uint32_t sb = sbase + st * (STG_EL * 2);
#pragma unroll
        for (int i = 0; i < 2; i++) {
            int u = tid + i * 256;             // 0..511
            int row = u >> 2, seg = (u & 3) * 8;
            uint32_t off = (uint32_t)(row * 80 + seg * 2);   // bytes
            size_t ga = (size_t)(m0 + row) * K + k0 + seg;
            size_t gb = (size_t)(n0 + row) * K + k0 + seg;
            cp16(sb + 0                + off, Ah + ga);
            cp16(sb + ARR_EL * 2       + off, Al + ga);
            cp16(sb + ARR_EL * 4       + off, Bh + gb);
            cp16(sb + ARR_EL * 6       + off, Bl + gb);
        }
    };

    float acc[4][4][4];
#pragma unroll
    for (int i = 0; i < 4; i++)
#pragma unroll
        for (int j = 0; j < 4; j++)
#pragma unroll
            for (int e = 0; e < 4; e++) acc[i][j][e] = 0.0f;

    load_chunk(0, 0);
    CP_COMMIT();

    for (int kc = 0; kc < KC; kc++) {
        if (kc + 1 < KC) { load_chunk(kc + 1, (kc + 1) & 1); CP_COMMIT(); CP_WAIT(1); }
        else             { CP_WAIT(0); }
        __syncthreads();

        const bf16* S = smem + (kc & 1) * STG_EL;
        const bf16* SA_h = S;
        const bf16* SA_l = S + ARR_EL;
        const bf16* SB_h = S + 2 * ARR_EL;
        const bf16* SB_l = S + 3 * ARR_EL;

#pragma unroll
        for (int ks = 0; ks < 2; ks++) {
            int kb = ks * 16;
            uint32_t bh[4][2], bl[4][2];
#pragma unroll
            for (int nf = 0; nf < 4; nf++) {
                int n = wn * 32 + nf * 8 + grp;
                bh[nf][0] = *(const uint32_t*)(SB_h + n * 40 + kb + 2 * tg);
                bh[nf][1] = *(const uint32_t*)(SB_h + n * 40 + kb + 2 * tg + 8);
                bl[nf][0] = *(const uint32_t*)(SB_l + n * 40 + kb + 2 * tg);
                bl[nf][1] = *(const uint32_t*)(SB_l + n * 40 + kb + 2 * tg + 8);
            }
            uint32_t a[4][4];
#pragma unroll
            for (int mf = 0; mf < 4; mf++) {
                int r = wm * 64 + mf * 16 + grp;
                a[mf][0] = *(const uint32_t*)(SA_h + r * 40       + kb + 2 * tg);
                a[mf][1] = *(const uint32_t*)(SA_h + (r + 8) * 40 + kb + 2 * tg);
                a[mf][2] = *(const uint32_t*)(SA_h + r * 40       + kb + 2 * tg + 8);
                a[mf][3] = *(const uint32_t*)(SA_h + (r + 8) * 40 + kb + 2 * tg + 8);
            }
#pragma unroll
            for (int mf = 0; mf < 4; mf++)
#pragma unroll
                for (int nf = 0; nf < 4; nf++) {
                    MMA_BF16(acc[mf][nf], a[mf], bh[nf]);
                    MMA_BF16(acc[mf][nf], a[mf], bl[nf]);
                }
#pragma unroll
            for (int mf = 0; mf < 4; mf++) {
                int r = wm * 64 + mf * 16 + grp;
                a[mf][0] = *(const uint32_t*)(SA_l + r * 40       + kb + 2 * tg);
                a[mf][1] = *(const uint32_t*)(SA_l + (r + 8) * 40 + kb + 2 * tg);
                a[mf][2] = *(const uint32_t*)(SA_l + r * 40       + kb + 2 * tg + 8);
                a[mf][3] = *(const uint32_t*)(SA_l + (r + 8) * 40 + kb + 2 * tg + 8);
            }
#pragma unroll
            for (int mf = 0; mf < 4; mf++)
#pragma unroll
                for (int nf = 0; nf < 4; nf++)
                    MMA_BF16(acc[mf][nf], a[mf], bh[nf]);
        }
        __syncthreads();
    }

    // epilogue
#pragma unroll
    for (int mf = 0; mf < 4; mf++) {
        int r = wm * 64 + mf * 16 + grp;
#pragma unroll
        for (int nf = 0; nf < 4; nf++) {
            int c = n0 + wn * 32 + nf * 8 + 2 * tg;
            float b0v = 0.0f, b1v = 0.0f;
            if (BIAS) { b0v = bias[c]; b1v = bias[c + 1]; }
            float v0 = acc[mf][nf][0] * alpha + b0v;
            float v1 = acc[mf][nf][1] * alpha + b1v;
            float v2 = acc[mf][nf][2] * alpha + b0v;
            float v3 = acc[mf][nf][3] * alpha + b1v;
            if (LEAKY) {
                v0 = (v0 >= 0.0f) ? v0 : NEG_SLOPE * v0;
                v1 = (v1 >= 0.0f) ? v1 : NEG_SLOPE * v1;
                v2 = (v2 >= 0.0f) ? v2 : NEG_SLOPE * v2;
                v3 = (v3 >= 0.0f) ? v3 : NEG_SLOPE * v3;
            }
            size_t o0 = bz * sC + (size_t)(m0 + r) * N + c;
            size_t o1 = bz * sC + (size_t)(m0 + r + 8) * N + c;
            if (OUTSPLIT) {
                bf16 h0 = __float2bfloat16(v0), h1 = __float2bfloat16(v1);
                bf16 h2 = __float2bfloat16(v2), h3 = __float2bfloat16(v3);
                *(__nv_bfloat162*)(Chi + o0) = __nv_bfloat162(h0, h1);
                *(__nv_bfloat162*)(Chi + o1) = __nv_bfloat162(h2, h3);
                *(__nv_bfloat162*)(Clo + o0) = __nv_bfloat162(
                    __float2bfloat16(v0 - __bfloat162float(h0)),
                    __float2bfloat16(v1 - __bfloat162float(h1)));
                *(__nv_bfloat162*)(Clo + o1) = __nv_bfloat162(
                    __float2bfloat16(v2 - __bfloat162float(h2)),
                    __float2bfloat16(v3 - __bfloat162float(h3)));
            } else {
                *(float2*)(C + o0) = make_float2(v0, v1);
                *(float2*)(C + o1) = make_float2(v2, v3);
            }
        }
    }
}

// ---------------- fp32 -> bf16 hi/lo split ----------------------------------
__global__ void convert_hilo(const float* __restrict__ x,
                             bf16* __restrict__ hi, bf16* __restrict__ lo)
{
    int i = blockIdx.x * blockDim.x + threadIdx.x;
    float v = x[i];
    bf16 h = __float2bfloat16(v);
    hi[i] = h;
    lo[i] = __float2bfloat16(v - __bfloat162float(h));
}

// transpose W[K][N] -> hi/lo [N][K]
__global__ void transpose_convert(const float* __restrict__ W,
                                  bf16* __restrict__ hi, bf16* __restrict__ lo,
                                  int K, int N)
{
    __shared__ float tile[32][33];
    int n0 = blockIdx.x * 32, k0 = blockIdx.y * 32;
    int tx = threadIdx.x, ty = threadIdx.y;   // 32 x 8
#pragma unroll
    for (int i = 0; i < 4; i++)
        tile[ty + i * 8][tx] = W[(size_t)(k0 + ty + i * 8) * N + n0 + tx];
    __syncthreads();
#pragma unroll
    for (int i = 0; i < 4; i++) {
        float x = tile[tx][ty + i * 8];
        bf16 h = __float2bfloat16(x);
        size_t o = (size_t)(n0 + ty + i * 8) * K + k0 + tx;
        hi[o] = h;
        lo[o] = __float2bfloat16(x - __bfloat162float(h));
    }
}

// ---------------- embedding -------------------------------------------------
__global__ void embed_kernel(const int* __restrict__ idx,
                             const float* __restrict__ tok,
                             const float* __restrict__ pos,
                             float* __restrict__ x)
{
    int row = blockIdx.x;
    int t   = row & (TT - 1);
    int token = idx[row];
    const float4* tp = (const float4*)(tok + (size_t)token * HH);
    const float4* pp = (const float4*)(pos + (size_t)t * HH);
    float4* xp = (float4*)(x + (size_t)row * HH);
    int i = threadIdx.x;
    float4 a = tp[i], b = pp[i];
    xp[i] = make_float4(a.x + b.x, a.y + b.y, a.z + b.z, a.w + b.w);
}

// ---------------- reductions ------------------------------------------------
__device__ __forceinline__ float warpMax(float v) {
#pragma unroll
    for (int o = 16; o > 0; o >>= 1) v = fmaxf(v, __shfl_xor_sync(0xffffffffu, v, o));
    return v;
}
__device__ __forceinline__ float warpSum(float v) {
#pragma unroll
    for (int o = 16; o > 0; o >>= 1) v += __shfl_xor_sync(0xffffffffu, v, o);
    return v;
}
__device__ float blockMax(float v) {
    __shared__ float sh[8];
    int lane = threadIdx.x & 31, w = threadIdx.x >> 5;
    v = warpMax(v);
    if (lane == 0) sh[w] = v;
    __syncthreads();
    if (w == 0) {
        float u = (lane < 8) ? sh[lane] : -INFINITY;
        u = warpMax(u);
        if (lane == 0) sh[0] = u;
    }
    __syncthreads();
    float r = sh[0];
    __syncthreads();
    return r;
}
__device__ float blockSum(float v) {
    __shared__ float sh[8];
    int lane = threadIdx.x & 31, w = threadIdx.x >> 5;
    v = warpSum(v);
    if (lane == 0) sh[w] = v;
    __syncthreads();
    if (w == 0) {
        float u = (lane < 8) ? sh[lane] : 0.0f;
        u = warpSum(u);
        if (lane == 0) sh[0] = u;
    }
    __syncthreads();
    float r = sh[0];
    __syncthreads();
    return r;
}

// ------------ causal softmax: fp32 scores -> bf16 hi/lo weights -------------
__global__ void softmax_causal_split(const float* __restrict__ s,
                                     bf16* __restrict__ whi, bf16* __restrict__ wlo)
{
    int row = blockIdx.x;
    int b = row >> 11;
    int t = row & (TT - 1);
    size_t off = (size_t)b * TT * TT + (size_t)t * TT;
    const float* p = s + off;
    int tid = threadIdx.x;

    float m = -INFINITY;
    for (int i = tid; i <= t; i += 256) m = fmaxf(m, p[i]);
    m = blockMax(m);

    float sum = 0.0f;
    for (int i = tid; i <= t; i += 256) sum += expf(p[i] - m);
    sum = blockSum(sum);

    float inv = 1.0f / sum;
    for (int i = tid; i < TT; i += 256) {
        float w = (i <= t) ? expf(p[i] - m) * inv : 0.0f;
        bf16 h = __float2bfloat16(w);
        whi[off + i] = h;
        wlo[off + i] = __float2bfloat16(w - __bfloat162float(h));
    }
}

// ---------------- cross entropy ---------------------------------------------
__global__ void ce_rows(const float* __restrict__ logits,
                        const int* __restrict__ tgt,
                        float* __restrict__ rl)
{
    int row = blockIdx.x;
    const float* p = logits + (size_t)row * VV;
    int tid = threadIdx.x;

    float m = -INFINITY;
    for (int i = tid; i < VV; i += 256) m = fmaxf(m, p[i]);
    m = blockMax(m);

    float s = 0.0f;
    for (int i = tid; i < VV; i += 256) s += expf(p[i] - m);
    s = blockSum(s);

    if (tid == 0) {
        float lse = m + logf(s);
        rl[row] = lse - p[tgt[row]];
    }
}

__global__ void loss_reduce(const float* __restrict__ rl, float* __restrict__ out)
{
    int tid = threadIdx.x;
    float s = 0.0f;
    for (int i = tid; i < MM; i += 256) s += rl[i];
    s = blockSum(s);
    if (tid == 0) out[0] = s / (float)MM;
}

// ---------------- driver ----------------------------------------------------
#define SMEM_BYTES (2 * STG_EL * 2)   // 81920

extern "C" void kernel_launch(void* const* d_in, const int* in_sizes, int n_in,
                              void* d_out, int out_size)
{
    const int*   idx = (const int*)  d_in[0];
    const int*   tgt = (const int*)  d_in[1];
    const float* tok = (const float*)d_in[2];
    const float* pos = (const float*)d_in[3];
    const float* wq  = (const float*)d_in[4];
    const float* wk  = (const float*)d_in[5];
    const float* wv  = (const float*)d_in[6];
    const float* hw  = (const float*)d_in[7];
    const float* hb  = (const float*)d_in[8];
    const float* lw  = (const float*)d_in[9];
    const float* lb  = (const float*)d_in[10];
    float* out = (float*)d_out;

    float *x, *v, *s, *rl;
    bf16 *ahi, *alo, *a2hi, *a2lo, *qhi, *qlo, *khi, *klo, *vthi, *vtlo;
    bf16 *shi, *slo, *whi, *wlo, *bhi, *blo;
    cudaGetSymbolAddress((void**)&x,    g_x);
    cudaGetSymbolAddress((void**)&v,    g_v);
    cudaGetSymbolAddress((void**)&s,    g_s);
    cudaGetSymbolAddress((void**)&rl,   g_rowloss);
    cudaGetSymbolAddress((void**)&ahi,  g_ahi);
    cudaGetSymbolAddress((void**)&alo,  g_alo);
    cudaGetSymbolAddress((void**)&a2hi, g_a2hi);
    cudaGetSymbolAddress((void**)&a2lo, g_a2lo);
    cudaGetSymbolAddress((void**)&qhi,  g_qhi);
    cudaGetSymbolAddress((void**)&qlo,  g_qlo);
    cudaGetSymbolAddress((void**)&khi,  g_khi);
    cudaGetSymbolAddress((void**)&klo,  g_klo);
    cudaGetSymbolAddress((void**)&vthi, g_vthi);
    cudaGetSymbolAddress((void**)&vtlo, g_vtlo);
    cudaGetSymbolAddress((void**)&shi,  g_shi);
    cudaGetSymbolAddress((void**)&slo,  g_slo);
    cudaGetSymbolAddress((void**)&whi,  g_whi);
    cudaGetSymbolAddress((void**)&wlo,  g_wlo);
    cudaGetSymbolAddress((void**)&bhi,  g_bhi);
    cudaGetSymbolAddress((void**)&blo,  g_blo);

    // raise dynamic smem limit for every instantiation used
    cudaFuncSetAttribute(mma_gemm<false,false,false,false,true >, cudaFuncAttributeMaxDynamicSharedMemorySize, SMEM_BYTES);
    cudaFuncSetAttribute(mma_gemm<false,false,false,false,false>, cudaFuncAttributeMaxDynamicSharedMemorySize, SMEM_BYTES);
    cudaFuncSetAttribute(mma_gemm<true ,false,false,false,false>, cudaFuncAttributeMaxDynamicSharedMemorySize, SMEM_BYTES);
    cudaFuncSetAttribute(mma_gemm<false,true ,false,false,true >, cudaFuncAttributeMaxDynamicSharedMemorySize, SMEM_BYTES);
    cudaFuncSetAttribute(mma_gemm<false,false,true ,true ,true >, cudaFuncAttributeMaxDynamicSharedMemorySize, SMEM_BYTES);
    cudaFuncSetAttribute(mma_gemm<false,false,true ,false,false>, cudaFuncAttributeMaxDynamicSharedMemorySize, SMEM_BYTES);

    dim3 tb(32, 8);
    const size_t WSZ = (size_t)HH * HH;

    // 0) weight preprocessing
    transpose_convert<<<dim3(HH/32, HH/32), tb>>>(wq, whi + 0*WSZ, wlo + 0*WSZ, HH, HH);
    transpose_convert<<<dim3(HH/32, HH/32), tb>>>(wk, whi + 1*WSZ, wlo + 1*WSZ, HH, HH);
    transpose_convert<<<dim3(HH/32, HH/32), tb>>>(wv, whi + 2*WSZ, wlo + 2*WSZ, HH, HH);
    for (int l = 0; l < LL; l++)
        transpose_convert<<<dim3(HH/32, HH/32), tb>>>(hw + l*WSZ, whi + (3+l)*WSZ, wlo + (3+l)*WSZ, HH, HH);
    transpose_convert<<<dim3(VV/32, HH/32), tb>>>(lw, bhi, blo, HH, VV);

    // 1) embeddings + split
    embed_kernel<<<MM, 256>>>(idx, tok, pos, x);
    convert_hilo<<<(MM*HH)/256, 256>>>(x, ahi, alo);

    // 2) QKV (q,k split-out; v fp32 for transpose)
    dim3 g1(MM/128, HH/128);
    mma_gemm<false,false,false,false,true ><<<g1, 256, SMEM_BYTES>>>(ahi, alo, whi+0*WSZ, wlo+0*WSZ, nullptr, nullptr, qhi, qlo, HH, HH, 0,0,0, 1.0f);
    mma_gemm<false,false,false,false,true ><<<g1, 256, SMEM_BYTES>>>(ahi, alo, whi+1*WSZ, wlo+1*WSZ, nullptr, nullptr, khi, klo, HH, HH, 0,0,0, 1.0f);
    mma_gemm<false,false,false,false,false><<<g1, 256, SMEM_BYTES>>>(ahi, alo, whi+2*WSZ, wlo+2*WSZ, nullptr, v, nullptr, nullptr, HH, HH, 0,0,0, 1.0f);

    // 3) V^T per batch: [T,H] -> [H,T] hi/lo
    for (int b = 0; b < BB; b++)
        transpose_convert<<<dim3(HH/32, TT/32), tb>>>(v + (size_t)b*TT*HH,
            vthi + (size_t)b*HH*TT, vtlo + (size_t)b*HH*TT, TT, HH);

    // 4) scores = Q@K^T * H^-0.5 on tensor cores (causal tile skip)
    mma_gemm<true,false,false,false,false><<<dim3(TT/128, TT/128, BB), 256, SMEM_BYTES>>>(
        qhi, qlo, khi, klo, nullptr, s, nullptr, nullptr, TT, HH,
        (size_t)TT*HH, (size_t)TT*HH, (size_t)TT*TT, 0.03125f);

    // 5) causal softmax -> bf16 hi/lo weights
    softmax_causal_split<<<MM, 256>>>(s, shi, slo);

    // 6) attn = wei @ V on tensor cores (K truncated causally), split-out
    mma_gemm<false,true,false,false,true><<<dim3(TT/128, HH/128, BB), 256, SMEM_BYTES>>>(
        shi, slo, vthi, vtlo, nullptr, nullptr, ahi, alo, HH, TT,
        (size_t)TT*TT, (size_t)HH*TT, (size_t)TT*HH, 1.0f);

    // 7) MLP stack (bias + LeakyReLU fused, split-out ping-pong)
    bf16 *curh = ahi, *curl = alo, *nxth = a2hi, *nxtl = a2lo;
    for (int l = 0; l < LL; l++) {
        mma_gemm<false,false,true,true,true><<<g1, 256, SMEM_BYTES>>>(
            curh, curl, whi + (3+l)*WSZ, wlo + (3+l)*WSZ, hb + (size_t)l*HH,
            nullptr, nxth, nxtl, HH, HH, 0,0,0, 1.0f);
        bf16* t1 = curh; curh = nxth; nxth = t1;
        bf16* t2 = curl; curl = nxtl; nxtl = t2;
    }

    // 8) LM head (bias fused), logits -> d_out
    mma_gemm<false,false,true,false,false><<<dim3(MM/128, VV/128), 256, SMEM_BYTES>>>(
        curh, curl, bhi, blo, lb, out, nullptr, nullptr, VV, HH, 0,0,0, 1.0f);

    // 9) cross-entropy mean -> last output element
    ce_rows<<<MM, 256>>>(out, tgt, rl);
    loss_reduce<<<1, 256>>>(rl, out + (out_size - 1));
}

// round 6
// speedup vs baseline: 2.7755x; 1.0876x over previous
#include <cuda_runtime.h>
#include <cuda_bf16.h>
#include <math.h>
#include <stdint.h>

// Problem constants (SimpleLanguageModel: B=2, T=2048, H=1024, V=32000, L=4)
#define BB 2
#define TT 2048
#define HH 1024
#define VV 32000
#define LL 4
#define MM (BB*TT)          // 4096 rows
#define NEG_SLOPE 0.01f

typedef __nv_bfloat16 bf16;

// ---------------- scratch (no allocations allowed -> __device__ globals) ----
__device__ float g_x [(size_t)MM*HH];
__device__ float g_v [(size_t)MM*HH];
__device__ float g_s [(size_t)BB*TT*TT];
__device__ float g_rowloss[MM];
__device__ bf16 g_ahi [(size_t)MM*HH];
__device__ bf16 g_alo [(size_t)MM*HH];
__device__ bf16 g_a2hi[(size_t)MM*HH];
__device__ bf16 g_a2lo[(size_t)MM*HH];
__device__ bf16 g_qhi [(size_t)MM*HH];
__device__ bf16 g_qlo [(size_t)MM*HH];
__device__ bf16 g_khi [(size_t)MM*HH];
__device__ bf16 g_klo [(size_t)MM*HH];
__device__ bf16 g_vthi[(size_t)MM*HH];
__device__ bf16 g_vtlo[(size_t)MM*HH];
__device__ bf16 g_shi [(size_t)BB*TT*TT];
__device__ bf16 g_slo [(size_t)BB*TT*TT];
__device__ bf16 g_whi [(size_t)7*HH*HH];
__device__ bf16 g_wlo [(size_t)7*HH*HH];
__device__ bf16 g_bhi [(size_t)VV*HH];
__device__ bf16 g_blo [(size_t)VV*HH];

// =============== bf16x3 mma.sync GEMM: C[M,N] = alpha*A[M,K]@B[N,K]^T ======
#define MMA_BF16(d, a, b) \
    asm volatile("mma.sync.aligned.m16n8k16.row.col.f32.bf16.bf16.f32 " \
        "{%0,%1,%2,%3}, {%4,%5,%6,%7}, {%8,%9}, {%0,%1,%2,%3};" \
        : "+f"((d)[0]), "+f"((d)[1]), "+f"((d)[2]), "+f"((d)[3]) \
        : "r"((a)[0]), "r"((a)[1]), "r"((a)[2]), "r"((a)[3]), \
          "r"((b)[0]), "r"((b)[1]))

#define LDSM4(d0, d1, d2, d3, a) \
    asm volatile("ldmatrix.sync.aligned.m8n8.x4.shared.b16 {%0,%1,%2,%3}, [%4];" \
        : "=r"(d0), "=r"(d1), "=r"(d2), "=r"(d3) : "r"(a))

__device__ __forceinline__ void cp16(uint32_t dst, const void* src) {
    asm volatile("cp.async.cg.shared.global [%0], [%1], 16;" :: "r"(dst), "l"(src));
}
#define CP_COMMIT() asm volatile("cp.async.commit_group;" ::: "memory")
#define CP_WAIT(n)  asm volatile("cp.async.wait_group %0;" :: "n"(n) : "memory")

// smem: rows of 40 bf16 (80B); per stage: Ah, Al, Bh, Bl each 128 rows
#define STG_EL 20480
#define ARR_EL 5120
#define STG_B  (STG_EL*2)
#define ARR_B  (ARR_EL*2)

template<bool CAUSAL, bool KCAUS, bool BIAS, bool LEAKY, bool OUTSPLIT>
__global__ __launch_bounds__(256, 2)
void mma_gemm(const bf16* __restrict__ Ahi, const bf16* __restrict__ Alo,
              const bf16* __restrict__ Bhi, const bf16* __restrict__ Blo,
              const float* __restrict__ bias,
              float* __restrict__ C, bf16* __restrict__ Chi, bf16* __restrict__ Clo,
              int N, int K, size_t sA, size_t sB, size_t sC, float alpha)
{
    int bm = blockIdx.x, bn = blockIdx.y, bz = blockIdx.z;
    if (CAUSAL && bn > bm) return;
    const bf16* Ah = Ahi + bz * sA;  const bf16* Al = Alo + bz * sA;
    const bf16* Bh = Bhi + bz * sB;  const bf16* Bl = Blo + bz * sB;

    extern __shared__ bf16 smem[];
    uint32_t sbase = (uint32_t)__cvta_generic_to_shared(smem);

    int tid = threadIdx.x;
    int m0 = bm * 128, n0 = bn * 128;
    int lane = tid & 31, warp = tid >> 5;
    int wm = warp >> 2, wn = warp & 3;      // warp grid 2 (m) x 4 (n)
    int grp = lane >> 2, tg = lane & 3;

    int KC = K / 32;
    if (KCAUS) { int kcm = (m0 + 128) / 32; if (kcm < KC) KC = kcm; }

    // ldmatrix per-lane base offsets (bytes, relative to array start)
    // A: lanes 0-7 rows +0..7 col 0 | 8-15 rows +8..15 col 0 | 16-23 rows +0..7 col 8 | 24-31 rows +8..15 col 8
    uint32_t a_off = (uint32_t)(((wm * 64 + (lane & 15)) * 40 + (lane >> 4) * 8) * 2);
    // B: lanes 0-7 rows +0..7 col 0 | 8-15 rows +0..7 col 8 | 16-23 rows +8..15 col 0 | 24-31 rows +8..15 col 8
    uint32_t b_off = (uint32_t)(((wn * 32 + ((lane >> 4) << 3) + (lane & 7)) * 40 + ((lane & 8) ? 8 : 0)) * 2);

    auto load_chunk = [&](int kc, int st) {
        int k0 = kc * 32;
        uint32_t sb = sbase + st * STG_B;
#pragma unroll
        for (int i = 0; i < 2; i++) {
            int u = tid + i * 256;
            int row = u >> 2, seg = (u & 3) * 8;
            uint32_t off = (uint32_t)(row * 80 + seg * 2);
            size_t ga = (size_t)(m0 + row) * K + k0 + seg;
            size_t gb = (size_t)(n0 + row) * K + k0 + seg;
            cp16(sb + 0         + off, Ah + ga);
            cp16(sb + ARR_B     + off, Al + ga);
            cp16(sb + 2 * ARR_B + off, Bh + gb);
            cp16(sb + 3 * ARR_B + off, Bl + gb);
        }
    };

    float acc[4][4][4];
#pragma unroll
    for (int i = 0; i < 4; i++)
#pragma unroll
        for (int j = 0; j < 4; j++)
#pragma unroll
            for (int e = 0; e < 4; e++) acc[i][j][e] = 0.0f;

    load_chunk(0, 0);
    CP_COMMIT();

    for (int kc = 0; kc < KC; kc++) {
        if (kc + 1 < KC) { load_chunk(kc + 1, (kc + 1) & 1); CP_COMMIT(); CP_WAIT(1); }
        else             { CP_WAIT(0); }
        __syncthreads();

        uint32_t S = sbase + (kc & 1) * STG_B;
        uint32_t pAh = S + a_off;
        uint32_t pAl = S + ARR_B + a_off;
        uint32_t pBh = S + 2 * ARR_B + b_off;
        uint32_t pBl = S + 3 * ARR_B + b_off;

#pragma unroll
        for (int ks = 0; ks < 2; ks++) {
            uint32_t kbb = ks * 32;              // kb*2 bytes (kb = 0/16 elements)
            uint32_t bh[4][2], bl[4][2], a[4][4];

            LDSM4(bh[0][0], bh[0][1], bh[1][0], bh[1][1], pBh + kbb);
            LDSM4(bh[2][0], bh[2][1], bh[3][0], bh[3][1], pBh + 16 * 80 + kbb);
            LDSM4(bl[0][0], bl[0][1], bl[1][0], bl[1][1], pBl + kbb);
            LDSM4(bl[2][0], bl[2][1], bl[3][0], bl[3][1], pBl + 16 * 80 + kbb);

#pragma unroll
            for (int mf = 0; mf < 4; mf++)
                LDSM4(a[mf][0], a[mf][1], a[mf][2], a[mf][3], pAh + mf * (16 * 80) + kbb);

#pragma unroll
            for (int mf = 0; mf < 4; mf++)
#pragma unroll
                for (int nf = 0; nf < 4; nf++)
                    MMA_BF16(acc[mf][nf], a[mf], bh[nf]);
#pragma unroll
            for (int mf = 0; mf < 4; mf++)
#pragma unroll
                for (int nf = 0; nf < 4; nf++)
                    MMA_BF16(acc[mf][nf], a[mf], bl[nf]);

#pragma unroll
            for (int mf = 0; mf < 4; mf++)
                LDSM4(a[mf][0], a[mf][1], a[mf][2], a[mf][3], pAl + mf * (16 * 80) + kbb);

#pragma unroll
            for (int mf = 0; mf < 4; mf++)
#pragma unroll
                for (int nf = 0; nf < 4; nf++)
                    MMA_BF16(acc[mf][nf], a[mf], bh[nf]);
        }
        __syncthreads();
    }

    // epilogue
#pragma unroll
    for (int mf = 0; mf < 4; mf++) {
        int r = wm * 64 + mf * 16 + grp;
#pragma unroll
        for (int nf = 0; nf < 4; nf++) {
            int c = n0 + wn * 32 + nf * 8 + 2 * tg;
            float b0v = 0.0f, b1v = 0.0f;
            if (BIAS) { b0v = bias[c]; b1v = bias[c + 1]; }
            float v0 = acc[mf][nf][0] * alpha + b0v;
            float v1 = acc[mf][nf][1] * alpha + b1v;
            float v2 = acc[mf][nf][2] * alpha + b0v;
            float v3 = acc[mf][nf][3] * alpha + b1v;
            if (LEAKY) {
                v0 = (v0 >= 0.0f) ? v0 : NEG_SLOPE * v0;
                v1 = (v1 >= 0.0f) ? v1 : NEG_SLOPE * v1;
                v2 = (v2 >= 0.0f) ? v2 : NEG_SLOPE * v2;
                v3 = (v3 >= 0.0f) ? v3 : NEG_SLOPE * v3;
            }
            size_t o0 = bz * sC + (size_t)(m0 + r) * N + c;
            size_t o1 = bz * sC + (size_t)(m0 + r + 8) * N + c;
            if (OUTSPLIT) {
                bf16 h0 = __float2bfloat16(v0), h1 = __float2bfloat16(v1);
                bf16 h2 = __float2bfloat16(v2), h3 = __float2bfloat16(v3);
                *(__nv_bfloat162*)(Chi + o0) = __nv_bfloat162(h0, h1);
                *(__nv_bfloat162*)(Chi + o1) = __nv_bfloat162(h2, h3);
                *(__nv_bfloat162*)(Clo + o0) = __nv_bfloat162(
                    __float2bfloat16(v0 - __bfloat162float(h0)),
                    __float2bfloat16(v1 - __bfloat162float(h1)));
                *(__nv_bfloat162*)(Clo + o1) = __nv_bfloat162(
                    __float2bfloat16(v2 - __bfloat162float(h2)),
                    __float2bfloat16(v3 - __bfloat162float(h3)));
            } else {
                *(float2*)(C + o0) = make_float2(v0, v1);
                *(float2*)(C + o1) = make_float2(v2, v3);
            }
        }
    }
}

// ---------------- fp32 -> bf16 hi/lo split ----------------------------------
__global__ void convert_hilo(const float* __restrict__ x,
                             bf16* __restrict__ hi, bf16* __restrict__ lo)
{
    int i = blockIdx.x * blockDim.x + threadIdx.x;
    float v = x[i];
    bf16 h = __float2bfloat16(v);
    hi[i] = h;
    lo[i] = __float2bfloat16(v - __bfloat162float(h));
}

// transpose W[K][N] -> hi/lo [N][K]
__global__ void transpose_convert(const float* __restrict__ W,
                                  bf16* __restrict__ hi, bf16* __restrict__ lo,
                                  int K, int N)
{
    __shared__ float tile[32][33];
    int n0 = blockIdx.x * 32, k0 = blockIdx.y * 32;
    int tx = threadIdx.x, ty = threadIdx.y;   // 32 x 8
#pragma unroll
    for (int i = 0; i < 4; i++)
        tile[ty + i * 8][tx] = W[(size_t)(k0 + ty + i * 8) * N + n0 + tx];
    __syncthreads();
#pragma unroll
    for (int i = 0; i < 4; i++) {
        float x = tile[tx][ty + i * 8];
        bf16 h = __float2bfloat16(x);
        size_t o = (size_t)(n0 + ty + i * 8) * K + k0 + tx;
        hi[o] = h;
        lo[o] = __float2bfloat16(x - __bfloat162float(h));
    }
}

// ---------------- embedding -------------------------------------------------
__global__ void embed_kernel(const int* __restrict__ idx,
                             const float* __restrict__ tok,
                             const float* __restrict__ pos,
                             float* __restrict__ x)
{
    int row = blockIdx.x;
    int t   = row & (TT - 1);
    int token = idx[row];
    const float4* tp = (const float4*)(tok + (size_t)token * HH);
    const float4* pp = (const float4*)(pos + (size_t)t * HH);
    float4* xp = (float4*)(x + (size_t)row * HH);
    int i = threadIdx.x;
    float4 a = tp[i], b = pp[i];
    xp[i] = make_float4(a.x + b.x, a.y + b.y, a.z + b.z, a.w + b.w);
}

// ---------------- reductions ------------------------------------------------
__device__ __forceinline__ float warpMax(float v) {
#pragma unroll
    for (int o = 16; o > 0; o >>= 1) v = fmaxf(v, __shfl_xor_sync(0xffffffffu, v, o));
    return v;
}
__device__ __forceinline__ float warpSum(float v) {
#pragma unroll
    for (int o = 16; o > 0; o >>= 1) v += __shfl_xor_sync(0xffffffffu, v, o);
    return v;
}
__device__ float blockMax(float v) {
    __shared__ float sh[8];
    int lane = threadIdx.x & 31, w = threadIdx.x >> 5;
    v = warpMax(v);
    if (lane == 0) sh[w] = v;
    __syncthreads();
    if (w == 0) {
        float u = (lane < 8) ? sh[lane] : -INFINITY;
        u = warpMax(u);
        if (lane == 0) sh[0] = u;
    }
    __syncthreads();
    float r = sh[0];
    __syncthreads();
    return r;
}
__device__ float blockSum(float v) {
    __shared__ float sh[8];
    int lane = threadIdx.x & 31, w = threadIdx.x >> 5;
    v = warpSum(v);
    if (lane == 0) sh[w] = v;
    __syncthreads();
    if (w == 0) {
        float u = (lane < 8) ? sh[lane] : 0.0f;
        u = warpSum(u);
        if (lane == 0) sh[0] = u;
    }
    __syncthreads();
    float r = sh[0];
    __syncthreads();
    return r;
}

// ------------ causal softmax: fp32 scores -> bf16 hi/lo weights -------------
__global__ void softmax_causal_split(const float* __restrict__ s,
                                     bf16* __restrict__ whi, bf16* __restrict__ wlo)
{
    int row = blockIdx.x;
    int b = row >> 11;
    int t = row & (TT - 1);
    size_t off = (size_t)b * TT * TT + (size_t)t * TT;
    const float* p = s + off;
    int tid = threadIdx.x;

    float m = -INFINITY;
    for (int i = tid; i <= t; i += 256) m = fmaxf(m, p[i]);
    m = blockMax(m);

    float sum = 0.0f;
    for (int i = tid; i <= t; i += 256) sum += expf(p[i] - m);
    sum = blockSum(sum);

    float inv = 1.0f / sum;
    for (int i = tid; i < TT; i += 256) {
        float w = (i <= t) ? expf(p[i] - m) * inv : 0.0f;
        bf16 h = __float2bfloat16(w);
        whi[off + i] = h;
        wlo[off + i] = __float2bfloat16(w - __bfloat162float(h));
    }
}

// ---------------- cross entropy ---------------------------------------------
__global__ void ce_rows(const float* __restrict__ logits,
                        const int* __restrict__ tgt,
                        float* __restrict__ rl)
{
    int row = blockIdx.x;
    const float* p = logits + (size_t)row * VV;
    int tid = threadIdx.x;

    float m = -INFINITY;
    for (int i = tid; i < VV; i += 256) m = fmaxf(m, p[i]);
    m = blockMax(m);

    float s = 0.0f;
    for (int i = tid; i < VV; i += 256) s += expf(p[i] - m);
    s = blockSum(s);

    if (tid == 0) {
        float lse = m + logf(s);
        rl[row] = lse - p[tgt[row]];
    }
}

__global__ void loss_reduce(const float* __restrict__ rl, float* __restrict__ out)
{
    int tid = threadIdx.x;
    float s = 0.0f;
    for (int i = tid; i < MM; i += 256) s += rl[i];
    s = blockSum(s);
    if (tid == 0) out[0] = s / (float)MM;
}

// ---------------- driver ----------------------------------------------------
#define SMEM_BYTES (2 * STG_B)   // 81920

extern "C" void kernel_launch(void* const* d_in, const int* in_sizes, int n_in,
                              void* d_out, int out_size)
{
    const int*   idx = (const int*)  d_in[0];
    const int*   tgt = (const int*)  d_in[1];
    const float* tok = (const float*)d_in[2];
    const float* pos = (const float*)d_in[3];
    const float* wq  = (const float*)d_in[4];
    const float* wk  = (const float*)d_in[5];
    const float* wv  = (const float*)d_in[6];
    const float* hw  = (const float*)d_in[7];
    const float* hb  = (const float*)d_in[8];
    const float* lw  = (const float*)d_in[9];
    const float* lb  = (const float*)d_in[10];
    float* out = (float*)d_out;

    float *x, *v, *s, *rl;
    bf16 *ahi, *alo, *a2hi, *a2lo, *qhi, *qlo, *khi, *klo, *vthi, *vtlo;
    bf16 *shi, *slo, *whi, *wlo, *bhi, *blo;
    cudaGetSymbolAddress((void**)&x,    g_x);
    cudaGetSymbolAddress((void**)&v,    g_v);
    cudaGetSymbolAddress((void**)&s,    g_s);
    cudaGetSymbolAddress((void**)&rl,   g_rowloss);
    cudaGetSymbolAddress((void**)&ahi,  g_ahi);
    cudaGetSymbolAddress((void**)&alo,  g_alo);
    cudaGetSymbolAddress((void**)&a2hi, g_a2hi);
    cudaGetSymbolAddress((void**)&a2lo, g_a2lo);
    cudaGetSymbolAddress((void**)&qhi,  g_qhi);
    cudaGetSymbolAddress((void**)&qlo,  g_qlo);
    cudaGetSymbolAddress((void**)&khi,  g_khi);
    cudaGetSymbolAddress((void**)&klo,  g_klo);
    cudaGetSymbolAddress((void**)&vthi, g_vthi);
    cudaGetSymbolAddress((void**)&vtlo, g_vtlo);
    cudaGetSymbolAddress((void**)&shi,  g_shi);
    cudaGetSymbolAddress((void**)&slo,  g_slo);
    cudaGetSymbolAddress((void**)&whi,  g_whi);
    cudaGetSymbolAddress((void**)&wlo,  g_wlo);
    cudaGetSymbolAddress((void**)&bhi,  g_bhi);
    cudaGetSymbolAddress((void**)&blo,  g_blo);

    cudaFuncSetAttribute(mma_gemm<false,false,false,false,true >, cudaFuncAttributeMaxDynamicSharedMemorySize, SMEM_BYTES);
    cudaFuncSetAttribute(mma_gemm<false,false,false,false,false>, cudaFuncAttributeMaxDynamicSharedMemorySize, SMEM_BYTES);
    cudaFuncSetAttribute(mma_gemm<true ,false,false,false,false>, cudaFuncAttributeMaxDynamicSharedMemorySize, SMEM_BYTES);
    cudaFuncSetAttribute(mma_gemm<false,true ,false,false,true >, cudaFuncAttributeMaxDynamicSharedMemorySize, SMEM_BYTES);
    cudaFuncSetAttribute(mma_gemm<false,false,true ,true ,true >, cudaFuncAttributeMaxDynamicSharedMemorySize, SMEM_BYTES);
    cudaFuncSetAttribute(mma_gemm<false,false,true ,false,false>, cudaFuncAttributeMaxDynamicSharedMemorySize, SMEM_BYTES);

    dim3 tb(32, 8);
    const size_t WSZ = (size_t)HH * HH;

    // 0) weight preprocessing
    transpose_convert<<<dim3(HH/32, HH/32), tb>>>(wq, whi + 0*WSZ, wlo + 0*WSZ, HH, HH);
    transpose_convert<<<dim3(HH/32, HH/32), tb>>>(wk, whi + 1*WSZ, wlo + 1*WSZ, HH, HH);
    transpose_convert<<<dim3(HH/32, HH/32), tb>>>(wv, whi + 2*WSZ, wlo + 2*WSZ, HH, HH);
    for (int l = 0; l < LL; l++)
        transpose_convert<<<dim3(HH/32, HH/32), tb>>>(hw + l*WSZ, whi + (3+l)*WSZ, wlo + (3+l)*WSZ, HH, HH);
    transpose_convert<<<dim3(VV/32, HH/32), tb>>>(lw, bhi, blo, HH, VV);

    // 1) embeddings + split
    embed_kernel<<<MM, 256>>>(idx, tok, pos, x);
    convert_hilo<<<(MM*HH)/256, 256>>>(x, ahi, alo);

    // 2) QKV
    dim3 g1(MM/128, HH/128);
    mma_gemm<false,false,false,false,true ><<<g1, 256, SMEM_BYTES>>>(ahi, alo, whi+0*WSZ, wlo+0*WSZ, nullptr, nullptr, qhi, qlo, HH, HH, 0,0,0, 1.0f);
    mma_gemm<false,false,false,false,true ><<<g1, 256, SMEM_BYTES>>>(ahi, alo, whi+1*WSZ, wlo+1*WSZ, nullptr, nullptr, khi, klo, HH, HH, 0,0,0, 1.0f);
    mma_gemm<false,false,false,false,false><<<g1, 256, SMEM_BYTES>>>(ahi, alo, whi+2*WSZ, wlo+2*WSZ, nullptr, v, nullptr, nullptr, HH, HH, 0,0,0, 1.0f);

    // 3) V^T per batch
    for (int b = 0; b < BB; b++)
        transpose_convert<<<dim3(HH/32, TT/32), tb>>>(v + (size_t)b*TT*HH,
            vthi + (size_t)b*HH*TT, vtlo + (size_t)b*HH*TT, TT, HH);

    // 4) scores = Q@K^T * H^-0.5 (causal tile skip)
    mma_gemm<true,false,false,false,false><<<dim3(TT/128, TT/128, BB), 256, SMEM_BYTES>>>(
        qhi, qlo, khi, klo, nullptr, s, nullptr, nullptr, TT, HH,
        (size_t)TT*HH, (size_t)TT*HH, (size_t)TT*TT, 0.03125f);

    // 5) causal softmax -> bf16 hi/lo
    softmax_causal_split<<<MM, 256>>>(s, shi, slo);

    // 6) attn = wei @ V (K truncated causally), split-out
    mma_gemm<false,true,false,false,true><<<dim3(TT/128, HH/128, BB), 256, SMEM_BYTES>>>(
        shi, slo, vthi, vtlo, nullptr, nullptr, ahi, alo, HH, TT,
        (size_t)TT*TT, (size_t)HH*TT, (size_t)TT*HH, 1.0f);

    // 7) MLP stack
    bf16 *curh = ahi, *curl = alo, *nxth = a2hi, *nxtl = a2lo;
    for (int l = 0; l < LL; l++) {
        mma_gemm<false,false,true,true,true><<<g1, 256, SMEM_BYTES>>>(
            curh, curl, whi + (3+l)*WSZ, wlo + (3+l)*WSZ, hb + (size_t)l*HH,
            nullptr, nxth, nxtl, HH, HH, 0,0,0, 1.0f);
        bf16* t1 = curh; curh = nxth; nxth = t1;
        bf16* t2 = curl; curl = nxtl; nxtl = t2;
    }

    // 8) LM head
    mma_gemm<false,false,true,false,false><<<dim3(MM/128, VV/128), 256, SMEM_BYTES>>>(
        curh, curl, bhi, blo, lb, out, nullptr, nullptr, VV, HH, 0,0,0, 1.0f);

    // 9) cross-entropy
    ce_rows<<<MM, 256>>>(out, tgt, rl);
    loss_reduce<<<1, 256>>>(rl, out + (out_size - 1));
}